// round 4
// baseline (speedup 1.0000x reference)
#include <cuda_runtime.h>
#include <math.h>

#define Nn 100000
#define Ee 800000
#define Dd 128
#define Ll 5
#define Cc 40
#define BN_EPS 1e-5f
#define NB ((Nn + 255) / 256)   // 391 scan blocks
#define SH_STRIDE 132           // padded sH row stride (floats): banks (4r+k)%32

// -------- device scratch (static, no runtime allocation) --------
__device__ float g_h   [(size_t)Nn * Dd];   // layer activations
__device__ float g_t   [(size_t)Nn * Dd];   // h @ W
__device__ float g_jk  [(size_t)Nn * Dd];   // running JumpingKnowledge max
__device__ float g_dinv[Nn];
__device__ int   g_deg [Nn];
__device__ int   g_off [Nn + 1];
__device__ int   g_cur [Nn];
__device__ int   g_bsum[NB];
__device__ int   g_csr_col[Ee];
__device__ int   g_ei  [2 * Ee];            // int32 edge index (converted)
__device__ int   g_is64;

// -------- packed f32x2 helpers (sm_100+: fma.rn.f32x2; ptxas won't auto-fuse) ----
__device__ __forceinline__ unsigned long long dup2(float x) {
    unsigned long long r;
    asm("mov.b64 %0, {%1, %1};" : "=l"(r) : "f"(x));
    return r;
}
__device__ __forceinline__ void ffma2(unsigned long long& d,
                                      unsigned long long a,
                                      unsigned long long b) {
    asm("fma.rn.f32x2 %0, %1, %2, %0;" : "+l"(d) : "l"(a), "l"(b));
}
__device__ __forceinline__ float2 unpk2(unsigned long long v) {
    float2 r;
    asm("mov.b64 {%0, %1}, %2;" : "=f"(r.x), "=f"(r.y) : "l"(v));
    return r;
}

// -------- dtype detection + conversion of edge_index --------
// If int64 (little-endian), high 32-bit words of all elements are 0
// (values < 100000). For int32 data those words are random node ids;
// 64 of them all zero has probability ~1e-160.
__global__ void detect_k(const int* __restrict__ raw) {
    if (threadIdx.x == 0 && blockIdx.x == 0) {
        int z = 0;
        #pragma unroll
        for (int j = 0; j < 64; j++) z |= raw[2 * j + 1];
        g_is64 = (z == 0) ? 1 : 0;
    }
}

__global__ void convert_k(const int* __restrict__ raw) {
    int i = blockIdx.x * blockDim.x + threadIdx.x;
    if (i < 2 * Ee) g_ei[i] = g_is64 ? raw[2 * i] : raw[i];
}

// -------- degree / normalization --------
__global__ void deg_k() {
    int i = blockIdx.x * blockDim.x + threadIdx.x;
    if (i < Ee) atomicAdd(&g_deg[g_ei[i]], 1);   // row = dst
}

__global__ void dinv_k() {
    int i = blockIdx.x * blockDim.x + threadIdx.x;
    if (i < Nn) g_dinv[i] = rsqrtf((float)g_deg[i] + 1.0f);
}

// -------- CSR build: exclusive scan of deg (2-level) + scatter --------
__global__ void scan_blk_k() {
    __shared__ int s[256];
    int i = blockIdx.x * 256 + threadIdx.x;
    int v = (i < Nn) ? g_deg[i] : 0;
    s[threadIdx.x] = v;
    __syncthreads();
    #pragma unroll
    for (int o = 1; o < 256; o <<= 1) {
        int t = (threadIdx.x >= o) ? s[threadIdx.x - o] : 0;
        __syncthreads();
        s[threadIdx.x] += t;
        __syncthreads();
    }
    if (i < Nn) g_off[i] = s[threadIdx.x] - v;       // exclusive within block
    if (threadIdx.x == 255) g_bsum[blockIdx.x] = s[255];
}

__global__ void scan_top_k() {                        // single block, 512 thr
    __shared__ int s[512];
    int v = (threadIdx.x < NB) ? g_bsum[threadIdx.x] : 0;
    s[threadIdx.x] = v;
    __syncthreads();
    #pragma unroll
    for (int o = 1; o < 512; o <<= 1) {
        int t = (threadIdx.x >= o) ? s[threadIdx.x - o] : 0;
        __syncthreads();
        s[threadIdx.x] += t;
        __syncthreads();
    }
    if (threadIdx.x < NB) g_bsum[threadIdx.x] = s[threadIdx.x] - v;  // exclusive
}

__global__ void scan_add_k() {
    int i = blockIdx.x * 256 + threadIdx.x;
    if (i < Nn) {
        int o = g_off[i] + g_bsum[blockIdx.x];
        g_off[i] = o;
        g_cur[i] = o;
    }
    if (i == 0) g_off[Nn] = Ee;
}

__global__ void scatter_k() {
    int e = blockIdx.x * blockDim.x + threadIdx.x;
    if (e < Ee) {
        int row = g_ei[e];
        int col = g_ei[Ee + e];
        int p = atomicAdd(&g_cur[row], 1);
        g_csr_col[p] = col;
    }
}

// -------- GEMM: g_t = hin @ W  (N x 128 @ 128 x 128), fp32 via f32x2 --------
// Block: 64 rows x 128 cols, 256 threads (16 tx x 16 ty).
// Thread: 4 rows x 8 cols (4 f32x2 pairs). W in smem [k][c]; H padded stride.
// Per k-step/thread: 16 FFMA2 + 4 dup + 2 LDS.128 + 4 LDS.32 = 26 issue slots
// vs 32 fma-pipe cycles -> fma-bound.
__global__ void gemm_k(const float* __restrict__ hin, const float* __restrict__ W) {
    extern __shared__ float sm[];
    float* sW = sm;                          // 128*128 floats (64 KB)
    float* sH = sm + 128 * 128;              // 64*SH_STRIDE floats (~33 KB)
    const int tid  = threadIdx.x;
    const int row0 = blockIdx.x * 64;

    // load W (4096 float4, 16 per thread)
    const float4* W4  = (const float4*)W;
    float4*       sW4 = (float4*)sW;
    #pragma unroll
    for (int i = 0; i < 16; i++) sW4[tid + 256 * i] = W4[tid + 256 * i];

    // load H tile (2048 float4, 8 per thread) into padded rows, zero-pad OOB
    const float4* H4 = (const float4*)hin;
    #pragma unroll
    for (int i = 0; i < 8; i++) {
        int idx = tid + 256 * i;
        int r   = idx >> 5;                  // 32 float4 per row
        int c4  = idx & 31;
        int gr  = row0 + r;
        ((float4*)(sH + r * SH_STRIDE))[c4] =
            (gr < Nn) ? H4[(size_t)gr * 32 + c4] : make_float4(0.f, 0.f, 0.f, 0.f);
    }
    __syncthreads();

    const int tx = tid & 15;                 // col group: cols 8*tx .. 8*tx+7
    const int ty = tid >> 4;                 // row group: rows 4*ty .. 4*ty+3
    const ulonglong2* sW2 = (const ulonglong2*)sW;  // 32 ulonglong2 per k-row

    unsigned long long acc[4][4];
    #pragma unroll
    for (int r = 0; r < 4; r++)
        #pragma unroll
        for (int p = 0; p < 4; p++) acc[r][p] = 0ull;

    const float* hbase = &sH[ty * 4 * SH_STRIDE];

    #pragma unroll 4
    for (int k = 0; k < 128; k++) {
        ulonglong2 wa = sW2[k * 32 + tx * 2];       // cols 8tx..8tx+3
        ulonglong2 wb = sW2[k * 32 + tx * 2 + 1];   // cols 8tx+4..8tx+7
        #pragma unroll
        for (int r = 0; r < 4; r++) {
            unsigned long long h2 = dup2(hbase[r * SH_STRIDE + k]);
            ffma2(acc[r][0], h2, wa.x);
            ffma2(acc[r][1], h2, wa.y);
            ffma2(acc[r][2], h2, wb.x);
            ffma2(acc[r][3], h2, wb.y);
        }
    }

    #pragma unroll
    for (int r = 0; r < 4; r++) {
        int gr = row0 + ty * 4 + r;
        if (gr < Nn) {
            float2 a0 = unpk2(acc[r][0]);
            float2 a1 = unpk2(acc[r][1]);
            float2 a2 = unpk2(acc[r][2]);
            float2 a3 = unpk2(acc[r][3]);
            float4* dst = (float4*)g_t + (size_t)gr * 32 + tx * 2;
            dst[0] = make_float4(a0.x, a0.y, a1.x, a1.y);
            dst[1] = make_float4(a2.x, a2.y, a3.x, a3.y);
        }
    }
}

// -------- fused gather-aggregate + epilogue: 1 warp / node --------
// agg = sum_{col in N(node)} dinv[node]*dinv[col] * t[col]
// y   = relu(s * (agg + t[node]/deg) + b'),  s = gamma*rsqrt(var+eps),
//                                            b' = s*(bias-mean) + beta
// h   = y ; jk = first ? y : max(jk, y)
__global__ void agg_post_k(const float* __restrict__ bias,
                           const float* __restrict__ gamma,
                           const float* __restrict__ beta,
                           const float* __restrict__ mean,
                           const float* __restrict__ var,
                           int first) {
    unsigned gtid = blockIdx.x * blockDim.x + threadIdx.x;
    unsigned node = gtid >> 5;
    unsigned lane = gtid & 31;
    if (node >= Nn) return;

    const int beg = g_off[node];
    const int end = g_off[node + 1];
    const float dr = g_dinv[node];
    const float4* T4 = (const float4*)g_t;

    float4 acc = make_float4(0.f, 0.f, 0.f, 0.f);
    int i = beg;
    // 4 independent gather chains (MLP>=4 hides L2/PTW latency)
    for (; i + 3 < end; i += 4) {
        int c0 = g_csr_col[i];
        int c1 = g_csr_col[i + 1];
        int c2 = g_csr_col[i + 2];
        int c3 = g_csr_col[i + 3];
        float n0 = dr * g_dinv[c0];
        float n1 = dr * g_dinv[c1];
        float n2 = dr * g_dinv[c2];
        float n3 = dr * g_dinv[c3];
        float4 v0 = T4[(size_t)c0 * 32 + lane];
        float4 v1 = T4[(size_t)c1 * 32 + lane];
        float4 v2 = T4[(size_t)c2 * 32 + lane];
        float4 v3 = T4[(size_t)c3 * 32 + lane];
        acc.x = fmaf(n0, v0.x, acc.x); acc.y = fmaf(n0, v0.y, acc.y);
        acc.z = fmaf(n0, v0.z, acc.z); acc.w = fmaf(n0, v0.w, acc.w);
        acc.x = fmaf(n1, v1.x, acc.x); acc.y = fmaf(n1, v1.y, acc.y);
        acc.z = fmaf(n1, v1.z, acc.z); acc.w = fmaf(n1, v1.w, acc.w);
        acc.x = fmaf(n2, v2.x, acc.x); acc.y = fmaf(n2, v2.y, acc.y);
        acc.z = fmaf(n2, v2.z, acc.z); acc.w = fmaf(n2, v2.w, acc.w);
        acc.x = fmaf(n3, v3.x, acc.x); acc.y = fmaf(n3, v3.y, acc.y);
        acc.z = fmaf(n3, v3.z, acc.z); acc.w = fmaf(n3, v3.w, acc.w);
    }
    for (; i < end; i++) {
        int c0 = g_csr_col[i];
        float n0 = dr * g_dinv[c0];
        float4 v0 = T4[(size_t)c0 * 32 + lane];
        acc.x = fmaf(n0, v0.x, acc.x); acc.y = fmaf(n0, v0.y, acc.y);
        acc.z = fmaf(n0, v0.z, acc.z); acc.w = fmaf(n0, v0.w, acc.w);
    }

    const float sn = dr * dr;                      // 1/deg
    size_t fi = (size_t)node * 32 + lane;
    float4 tv = T4[fi];
    float4 b4 = ((const float4*)bias )[lane];
    float4 gm = ((const float4*)gamma)[lane];
    float4 bt = ((const float4*)beta )[lane];
    float4 mn = ((const float4*)mean )[lane];
    float4 vr = ((const float4*)var  )[lane];

    // fold BN: s = gamma*rsqrt(var+eps); b' = s*(bias-mean)+beta
    float4 s4, bp;
    s4.x = gm.x * rsqrtf(vr.x + BN_EPS);  bp.x = fmaf(s4.x, b4.x - mn.x, bt.x);
    s4.y = gm.y * rsqrtf(vr.y + BN_EPS);  bp.y = fmaf(s4.y, b4.y - mn.y, bt.y);
    s4.z = gm.z * rsqrtf(vr.z + BN_EPS);  bp.z = fmaf(s4.z, b4.z - mn.z, bt.z);
    s4.w = gm.w * rsqrtf(vr.w + BN_EPS);  bp.w = fmaf(s4.w, b4.w - mn.w, bt.w);

    float4 y;
    y.x = fmaxf(fmaf(s4.x, fmaf(tv.x, sn, acc.x), bp.x), 0.f);
    y.y = fmaxf(fmaf(s4.y, fmaf(tv.y, sn, acc.y), bp.y), 0.f);
    y.z = fmaxf(fmaf(s4.z, fmaf(tv.z, sn, acc.z), bp.z), 0.f);
    y.w = fmaxf(fmaf(s4.w, fmaf(tv.w, sn, acc.w), bp.w), 0.f);

    ((float4*)g_h)[fi] = y;
    if (first) {
        ((float4*)g_jk)[fi] = y;
    } else {
        float4 j = ((float4*)g_jk)[fi];
        j.x = fmaxf(j.x, y.x); j.y = fmaxf(j.y, y.y);
        j.z = fmaxf(j.z, y.z); j.w = fmaxf(j.w, y.w);
        ((float4*)g_jk)[fi] = j;
    }
}

// -------- head: logits = jk @ lin_w + lin_b ; log_softmax. 1 warp / node --------
__global__ void final_k(const float* __restrict__ lin_w,
                        const float* __restrict__ lin_b,
                        float* __restrict__ out) {
    __shared__ float sw[Dd * Cc];   // 20 KB, [k][c]
    __shared__ float sb[Cc];
    const int tid = threadIdx.x;
    for (int i = tid; i < Dd * Cc; i += 256) sw[i] = lin_w[i];
    if (tid < Cc) sb[tid] = lin_b[tid];
    __syncthreads();

    int warp = tid >> 5, lane = tid & 31;
    int node = blockIdx.x * 8 + warp;
    if (node >= Nn) return;

    float acc0 = sb[lane];                           // class = lane
    float acc1 = (lane < 8) ? sb[32 + lane] : 0.f;   // class = 32+lane
    const float* hrow = &g_jk[(size_t)node * Dd];

    for (int kb = 0; kb < Dd; kb += 32) {
        float xchunk = hrow[kb + lane];
        #pragma unroll
        for (int j = 0; j < 32; j++) {
            float xv = __shfl_sync(0xffffffffu, xchunk, j);
            int k = kb + j;
            acc0 = fmaf(xv, sw[k * Cc + lane], acc0);
            if (lane < 8) acc1 = fmaf(xv, sw[k * Cc + 32 + lane], acc1);
        }
    }

    float m = (lane < 8) ? fmaxf(acc0, acc1) : acc0;
    #pragma unroll
    for (int o = 16; o >= 1; o >>= 1) m = fmaxf(m, __shfl_xor_sync(0xffffffffu, m, o));
    float e0 = expf(acc0 - m);
    float e1 = (lane < 8) ? expf(acc1 - m) : 0.f;
    float s  = e0 + e1;
    #pragma unroll
    for (int o = 16; o >= 1; o >>= 1) s += __shfl_xor_sync(0xffffffffu, s, o);
    float ls = logf(s);

    out[(size_t)node * Cc + lane] = acc0 - m - ls;
    if (lane < 8) out[(size_t)node * Cc + 32 + lane] = acc1 - m - ls;
}

// -------- host --------
extern "C" void kernel_launch(void* const* d_in, const int* in_sizes, int n_in,
                              void* d_out, int out_size) {
    const float* x        = (const float*)d_in[0];
    const int*   ei_raw   = (const int*)  d_in[1];
    const float* conv_w   = (const float*)d_in[2];
    const float* conv_b   = (const float*)d_in[3];
    const float* bn_gamma = (const float*)d_in[4];
    const float* bn_beta  = (const float*)d_in[5];
    const float* bn_mean  = (const float*)d_in[6];
    const float* bn_var   = (const float*)d_in[7];
    const float* lin_w    = (const float*)d_in[8];
    const float* lin_b    = (const float*)d_in[9];
    float* out = (float*)d_out;

    const int smem_bytes = (128 * 128 + 64 * SH_STRIDE) * 4;   // ~99 KB
    cudaFuncSetAttribute(gemm_k, cudaFuncAttributeMaxDynamicSharedMemorySize, smem_bytes);

    void *p_deg = nullptr, *p_h = nullptr;
    cudaGetSymbolAddress(&p_deg, g_deg);
    cudaGetSymbolAddress(&p_h,   g_h);

    // one-time per launch: edge index convert, degrees, CSR build
    cudaMemsetAsync(p_deg, 0, Nn * sizeof(int));
    detect_k<<<1, 32>>>(ei_raw);
    convert_k<<<(2 * Ee + 255) / 256, 256>>>(ei_raw);
    deg_k<<<(Ee + 255) / 256, 256>>>();
    dinv_k<<<(Nn + 255) / 256, 256>>>();
    scan_blk_k<<<NB, 256>>>();
    scan_top_k<<<1, 512>>>();
    scan_add_k<<<NB, 256>>>();
    scatter_k<<<(Ee + 255) / 256, 256>>>();

    for (int l = 0; l < Ll; l++) {
        const float* hin = (l == 0) ? x : (const float*)p_h;
        gemm_k<<<(Nn + 63) / 64, 256, smem_bytes>>>(hin, conv_w + (size_t)l * Dd * Dd);
        agg_post_k<<<(Nn * 32 + 255) / 256, 256>>>(conv_b + l * Dd, bn_gamma + l * Dd,
                                                   bn_beta + l * Dd, bn_mean + l * Dd,
                                                   bn_var + l * Dd, l == 0);
    }
    final_k<<<(Nn + 7) / 8, 256>>>(lin_w, lin_b, out);
}